// round 1
// baseline (speedup 1.0000x reference)
#include <cuda_runtime.h>
#include <cuda_bf16.h>
#include <math.h>

// Problem constants
#define NUM_TOKENS 16384
#define EMBED_DIM  4096
#define NUM_EXP    64
#define TOPK       2

// Tiling
#define TB      64      // tokens per block
#define KC      64      // K-chunk
#define THREADS 128
#define NBLK    (NUM_TOKENS / TB)   // 256
#define NCHUNK  (EMBED_DIM / KC)    // 64

// Output layout (flattened concat of reference return values, all fp32):
//   [0, 32768)        routing_weights [T,2]
//   [32768, 65536)    selected_experts [T,2] (as float)
//   [65536]           aux_loss
#define OUT_IDX_OFF (NUM_TOKENS * TOPK)
#define OUT_AUX_OFF (2 * NUM_TOKENS * TOPK)

__device__ float g_cnt[NUM_EXP];
__device__ float g_psum[NUM_EXP];

__device__ __forceinline__ void ffma2(unsigned long long& c,
                                      unsigned long long a,
                                      unsigned long long b) {
    // packed fp32x2 FMA (PTX ISA 8.6, sm_100+): 2 independent lane FMAs
    asm("fma.rn.f32x2 %0, %1, %2, %0;" : "+l"(c) : "l"(a), "l"(b));
}

__global__ void router_zero_kernel() {
    int t = threadIdx.x;
    if (t < NUM_EXP) { g_cnt[t] = 0.0f; g_psum[t] = 0.0f; }
}

__global__ __launch_bounds__(THREADS)
void router_main_kernel(const float* __restrict__ H,
                        const float* __restrict__ W,
                        float* __restrict__ out) {
    // smem tiles, 68-word pitch (16B-aligned rows, conflict-free LDS.128)
    __shared__ float hs[TB][68];
    __shared__ float ws[NUM_EXP][68];

    const int tid = threadIdx.x;
    const int eg  = tid & 7;    // expert group: experts eg + 8j
    const int ts  = tid >> 3;   // token slot:  tokens ts + 16*tt
    const int tb  = blockIdx.x * TB;

    // accumulators: [token tt][expert j], each a packed f32x2 partial pair
    unsigned long long acc[4][8];
#pragma unroll
    for (int tt = 0; tt < 4; ++tt)
#pragma unroll
        for (int j = 0; j < 8; ++j) acc[tt][j] = 0ull;

    for (int c = 0; c < NCHUNK; ++c) {
        const int k0 = c * KC;
        // cooperative load: 64 rows x 16 float4 for both H tile and W tile
#pragma unroll
        for (int i = 0; i < 8; ++i) {
            int f  = tid + (i << 7);       // 0..1023
            int r  = f >> 4;               // row 0..63
            int q4 = f & 15;               // float4 col
            float4 hv = *reinterpret_cast<const float4*>(
                H + (size_t)(tb + r) * EMBED_DIM + k0 + (q4 << 2));
            *reinterpret_cast<float4*>(&hs[r][q4 << 2]) = hv;
            float4 wv = *reinterpret_cast<const float4*>(
                W + (size_t)r * EMBED_DIM + k0 + (q4 << 2));
            *reinterpret_cast<float4*>(&ws[r][q4 << 2]) = wv;
        }
        __syncthreads();

#pragma unroll 4
        for (int q = 0; q < KC / 4; ++q) {
            ulonglong2 h2[4];
#pragma unroll
            for (int tt = 0; tt < 4; ++tt)
                h2[tt] = *reinterpret_cast<const ulonglong2*>(&hs[ts + 16 * tt][q << 2]);
#pragma unroll
            for (int j = 0; j < 8; ++j) {
                ulonglong2 w2 = *reinterpret_cast<const ulonglong2*>(&ws[eg + (j << 3)][q << 2]);
#pragma unroll
                for (int tt = 0; tt < 4; ++tt) {
                    ffma2(acc[tt][j], h2[tt].x, w2.x);
                    ffma2(acc[tt][j], h2[tt].y, w2.y);
                }
            }
        }
        __syncthreads();
    }

    // ---- epilogue: logits -> smem (overlay on hs, pitch 65 for conflict-free cols)
    float (*lg)[65] = reinterpret_cast<float(*)[65]>(&hs[0][0]);
#pragma unroll
    for (int tt = 0; tt < 4; ++tt)
#pragma unroll
        for (int j = 0; j < 8; ++j) {
            unsigned long long v = acc[tt][j];
            float lo = __uint_as_float((unsigned)(v & 0xffffffffull));
            float hi = __uint_as_float((unsigned)(v >> 32));
            lg[ts + 16 * tt][eg + (j << 3)] = lo + hi;
        }
    __syncthreads();

    if (tid < TB) {
        float* row = lg[tid];
        // top-1 (strict >, earliest index on ties — matches jax.lax.top_k)
        float m1 = -INFINITY; int i1 = 0;
#pragma unroll
        for (int e = 0; e < NUM_EXP; ++e) {
            float v = row[e];
            if (v > m1) { m1 = v; i1 = e; }
        }
        // top-2 excluding i1
        float m2 = -INFINITY; int i2 = 0;
#pragma unroll
        for (int e = 0; e < NUM_EXP; ++e) {
            if (e == i1) continue;
            float v = row[e];
            if (v > m2) { m2 = v; i2 = e; }
        }
        float d   = expf(m2 - m1);
        float inv = 1.0f / (1.0f + d);
        int g = tb + tid;
        out[2 * g]     = inv;       // softmax over [m1, m2], descending
        out[2 * g + 1] = d * inv;
        out[OUT_IDX_OFF + 2 * g]     = (float)i1;
        out[OUT_IDX_OFF + 2 * g + 1] = (float)i2;
        atomicAdd(&g_cnt[i1], 1.0f);
        atomicAdd(&g_cnt[i2], 1.0f);

        // full softmax over 64 experts (for P); overwrite row with probs
        float s = 0.0f;
#pragma unroll
        for (int e = 0; e < NUM_EXP; ++e) {
            float p = expf(row[e] - m1);
            row[e] = p;
            s += p;
        }
        float is = 1.0f / s;
#pragma unroll
        for (int e = 0; e < NUM_EXP; ++e) row[e] *= is;
    }
    __syncthreads();

    if (tid < NUM_EXP) {
        float s = 0.0f;
#pragma unroll
        for (int t = 0; t < TB; ++t) s += lg[t][tid];
        atomicAdd(&g_psum[tid], s);
    }
}

__global__ void router_aux_kernel(float* __restrict__ out) {
    __shared__ float red[NUM_EXP];
    int t = threadIdx.x;
    float f = g_cnt[t]  * (1.0f / (float)(NUM_TOKENS * TOPK));
    float P = g_psum[t] * (1.0f / (float)NUM_TOKENS);
    red[t] = (float)NUM_EXP * f * P;
    __syncthreads();
#pragma unroll
    for (int s = NUM_EXP / 2; s > 0; s >>= 1) {
        if (t < s) red[t] += red[t + s];
        __syncthreads();
    }
    if (t == 0) out[OUT_AUX_OFF] = red[0];
}

extern "C" void kernel_launch(void* const* d_in, const int* in_sizes, int n_in,
                              void* d_out, int out_size) {
    const float* H = (const float*)d_in[0];  // [16384, 4096] fp32
    const float* W = (const float*)d_in[1];  // [64, 4096]    fp32
    float* out = (float*)d_out;
    (void)in_sizes; (void)n_in; (void)out_size;

    router_zero_kernel<<<1, 64>>>();
    router_main_kernel<<<NBLK, THREADS>>>(H, W, out);
    router_aux_kernel<<<1, NUM_EXP>>>(out);
}

// round 4
// speedup vs baseline: 1.3929x; 1.3929x over previous
#include <cuda_runtime.h>
#include <math.h>
#include <cstdint>

// ---------------- problem constants ----------------
#define NUM_TOKENS 16384
#define EMBED_DIM  4096
#define NUM_EXP    64
#define TOPK       2

// ---------------- tiling ----------------
#define TPB     128                    // tokens per CTA (M)
#define KC      32                     // K elems per chunk
#define NCHUNK  (EMBED_DIM / KC)       // 128
#define THREADS 256                    // 8 warps
#define NBLK    (NUM_TOKENS / TPB)     // 128 CTAs

// smem (words): per stage A0[128][36], A1, B0[64][36], B1
#define PITCH   36
#define A0_W    0
#define A1_W    (128 * PITCH)          // 4608
#define B0_W    (2 * 128 * PITCH)      // 9216
#define B1_W    (B0_W + 64 * PITCH)    // 11520
#define STAGE_W (B1_W + 64 * PITCH)    // 13824 words = 55296 B
#define SMEM_DYN (2 * STAGE_W * 4)     // 110592 B

// output layout: [weights 2T][indices-as-float 2T][aux 1]
#define OUT_IDX_OFF (NUM_TOKENS * TOPK)
#define OUT_AUX_OFF (2 * NUM_TOKENS * TOPK)

__device__ float g_cnt[NUM_EXP];
__device__ float g_psum[NUM_EXP];
__device__ float g_W0[NUM_EXP * EMBED_DIM];
__device__ float g_W1[NUM_EXP * EMBED_DIM];

// tf32 convert: destination must be .b32 per PTX spec
__device__ __forceinline__ uint32_t to_tf32(float x) {
    uint32_t r;
    asm("cvt.rna.tf32.f32 %0, %1;" : "=r"(r) : "f"(x));
    return r;
}

__device__ __forceinline__ void mma_tf32(float* d, const uint32_t* a, const uint32_t* b) {
    asm volatile(
        "mma.sync.aligned.m16n8k8.row.col.f32.tf32.tf32.f32 "
        "{%0,%1,%2,%3}, {%4,%5,%6,%7}, {%8,%9}, {%0,%1,%2,%3};"
        : "+f"(d[0]), "+f"(d[1]), "+f"(d[2]), "+f"(d[3])
        : "r"(a[0]), "r"(a[1]), "r"(a[2]), "r"(a[3]), "r"(b[0]), "r"(b[1]));
}

// ---------------- prologue: zero accumulators + split W into tf32 limbs ----------------
__global__ void wsplit_kernel(const float* __restrict__ W) {
    if (blockIdx.x == 0 && threadIdx.x < NUM_EXP) {
        g_cnt[threadIdx.x] = 0.0f;
        g_psum[threadIdx.x] = 0.0f;
    }
    for (int i = blockIdx.x * blockDim.x + threadIdx.x; i < NUM_EXP * EMBED_DIM;
         i += gridDim.x * blockDim.x) {
        float x = W[i];
        uint32_t t0 = to_tf32(x);
        float t0f = __uint_as_float(t0);
        g_W0[i] = t0f;
        g_W1[i] = __uint_as_float(to_tf32(x - t0f));
    }
}

// ---------------- main kernel ----------------
__global__ __launch_bounds__(THREADS, 1)
void router_mma_kernel(const float* __restrict__ H, float* __restrict__ out) {
    extern __shared__ float dsm[];

    const int tid  = threadIdx.x;
    const int wid  = tid >> 5;
    const int lane = tid & 31;
    const int mg   = wid & 3;          // m-group: tokens mg*32..mg*32+31
    const int ng   = wid >> 2;         // n-group: experts ng*32..ng*32+31
    const int tb   = blockIdx.x * TPB;

    const float* __restrict__ Hbase = H + (size_t)tb * EMBED_DIM;

    // accumulators: [mt][nt][4]
    float acc[2][4][4];
#pragma unroll
    for (int mt = 0; mt < 2; ++mt)
#pragma unroll
        for (int nt = 0; nt < 4; ++nt)
#pragma unroll
            for (int r = 0; r < 4; ++r) acc[mt][nt][r] = 0.0f;

    // prefetch registers for one chunk
    float4 hreg[4], wreg[4];

#define LOAD_CHUNK(c)                                                           \
    do {                                                                        \
        const int k0 = (c) * KC;                                                \
        _Pragma("unroll")                                                       \
        for (int i = 0; i < 4; ++i) {                                           \
            int idx = tid + (i << 8);        /* 0..1023 */                      \
            int r = idx >> 3, q = idx & 7;                                      \
            hreg[i] = *reinterpret_cast<const float4*>(                         \
                Hbase + (size_t)r * EMBED_DIM + k0 + (q << 2));                 \
        }                                                                       \
        _Pragma("unroll")                                                       \
        for (int i = 0; i < 4; ++i) {                                           \
            int idx = tid + (i << 8);                                           \
            int limb = idx >> 9, idx2 = idx & 511;                              \
            int r = idx2 >> 3, q = idx2 & 7;                                    \
            const float* Wp = limb ? g_W1 : g_W0;                               \
            wreg[i] = *reinterpret_cast<const float4*>(                         \
                Wp + (size_t)r * EMBED_DIM + k0 + (q << 2));                    \
        }                                                                       \
    } while (0)

    LOAD_CHUNK(0);

    // per-thread fragment lds offsets (within a stage, in words)
    const int arow = (lane >> 2);      // 0..7
    const int acol = (lane & 3);       // 0..3

    for (int c = 0; c < NCHUNK; ++c) {
        float* sb = dsm + (c & 1) * STAGE_W;

        // ---- store limbs for chunk c from regs ----
#pragma unroll
        for (int i = 0; i < 4; ++i) {
            int idx = tid + (i << 8);
            int r = idx >> 3, q = idx & 7;
            int off = r * PITCH + (q << 2);
            float4 x = hreg[i];
            float a0 = __uint_as_float(to_tf32(x.x));
            float a1 = __uint_as_float(to_tf32(x.y));
            float a2 = __uint_as_float(to_tf32(x.z));
            float a3 = __uint_as_float(to_tf32(x.w));
            *reinterpret_cast<float4*>(sb + A0_W + off) = make_float4(a0, a1, a2, a3);
            *reinterpret_cast<float4*>(sb + A1_W + off) =
                make_float4(__uint_as_float(to_tf32(x.x - a0)),
                            __uint_as_float(to_tf32(x.y - a1)),
                            __uint_as_float(to_tf32(x.z - a2)),
                            __uint_as_float(to_tf32(x.w - a3)));
        }
#pragma unroll
        for (int i = 0; i < 4; ++i) {
            int idx = tid + (i << 8);
            int limb = idx >> 9, idx2 = idx & 511;
            int r = idx2 >> 3, q = idx2 & 7;
            int off = (limb ? B1_W : B0_W) + r * PITCH + (q << 2);
            *reinterpret_cast<float4*>(sb + off) = wreg[i];  // already tf32 limbs
        }

        if (c + 1 < NCHUNK) LOAD_CHUNK(c + 1);

        __syncthreads();

        // ---- MMA over chunk c ----
        const uint32_t* sbu = reinterpret_cast<const uint32_t*>(sb);
#pragma unroll
        for (int ks = 0; ks < 4; ++ks) {
            const int k0 = ks << 3;
            uint32_t af[2][2][4];   // [mt][limb][reg]
            uint32_t bf[4][2][2];   // [nt][limb][reg]
#pragma unroll
            for (int mt = 0; mt < 2; ++mt) {
                int rb = (mg << 5) + (mt << 4) + arow;
#pragma unroll
                for (int l = 0; l < 2; ++l) {
                    int base = (l ? A1_W : A0_W) + rb * PITCH + k0 + acol;
                    af[mt][l][0] = sbu[base];
                    af[mt][l][1] = sbu[base + 8 * PITCH];
                    af[mt][l][2] = sbu[base + 4];
                    af[mt][l][3] = sbu[base + 8 * PITCH + 4];
                }
            }
#pragma unroll
            for (int nt = 0; nt < 4; ++nt) {
                int nb = (ng << 5) + (nt << 3) + arow;
#pragma unroll
                for (int l = 0; l < 2; ++l) {
                    int base = (l ? B1_W : B0_W) + nb * PITCH + k0 + acol;
                    bf[nt][l][0] = sbu[base];
                    bf[nt][l][1] = sbu[base + 4];
                }
            }
#pragma unroll
            for (int mt = 0; mt < 2; ++mt)
#pragma unroll
                for (int nt = 0; nt < 4; ++nt) {
                    mma_tf32(acc[mt][nt], af[mt][0], bf[nt][0]);  // a0*b0
                    mma_tf32(acc[mt][nt], af[mt][0], bf[nt][1]);  // a0*b1
                    mma_tf32(acc[mt][nt], af[mt][1], bf[nt][0]);  // a1*b0
                }
        }
        __syncthreads();
    }

    // ---- write logits to smem: lg[128][65] ----
    float* lg = dsm;
#pragma unroll
    for (int mt = 0; mt < 2; ++mt) {
        int row0 = (mg << 5) + (mt << 4) + arow;
#pragma unroll
        for (int nt = 0; nt < 4; ++nt) {
            int col0 = (ng << 5) + (nt << 3) + (acol << 1);
            lg[row0 * 65 + col0]           = acc[mt][nt][0];
            lg[row0 * 65 + col0 + 1]       = acc[mt][nt][1];
            lg[(row0 + 8) * 65 + col0]     = acc[mt][nt][2];
            lg[(row0 + 8) * 65 + col0 + 1] = acc[mt][nt][3];
        }
    }
    __syncthreads();

    // ---- per-token epilogue (threads 0..127) ----
    if (tid < TPB) {
        const float* row = lg + tid * 65;
        float v[NUM_EXP];
#pragma unroll
        for (int e = 0; e < NUM_EXP; ++e) v[e] = row[e];

        float m1 = -INFINITY; int i1 = 0;
#pragma unroll
        for (int e = 0; e < NUM_EXP; ++e)
            if (v[e] > m1) { m1 = v[e]; i1 = e; }
        float m2 = -INFINITY; int i2 = 0;
#pragma unroll
        for (int e = 0; e < NUM_EXP; ++e) {
            if (e == i1) continue;
            if (v[e] > m2) { m2 = v[e]; i2 = e; }
        }
        float dlt = expf(m2 - m1);
        float inv = 1.0f / (1.0f + dlt);
        int g = tb + tid;
        out[2 * g]     = inv;
        out[2 * g + 1] = dlt * inv;
        out[OUT_IDX_OFF + 2 * g]     = (float)i1;
        out[OUT_IDX_OFF + 2 * g + 1] = (float)i2;
        atomicAdd(&g_cnt[i1], 1.0f);
        atomicAdd(&g_cnt[i2], 1.0f);

        float ssum = 0.0f;
#pragma unroll
        for (int e = 0; e < NUM_EXP; ++e) {
            float p = expf(v[e] - m1);
            v[e] = p;
            ssum += p;
        }
        float is = 1.0f / ssum;
        float* wrow = lg + tid * 65;   // overwrite with probs
#pragma unroll
        for (int e = 0; e < NUM_EXP; ++e) wrow[e] = v[e] * is;
    }
    __syncthreads();

    if (tid < NUM_EXP) {
        float s = 0.0f;
#pragma unroll
        for (int t = 0; t < TPB; ++t) s += lg[t * 65 + tid];
        atomicAdd(&g_psum[tid], s);
    }
}

// ---------------- aux loss finalize ----------------
__global__ void router_aux_kernel(float* __restrict__ out) {
    __shared__ float red[NUM_EXP];
    int t = threadIdx.x;
    float f = g_cnt[t]  * (1.0f / (float)(NUM_TOKENS * TOPK));
    float P = g_psum[t] * (1.0f / (float)NUM_TOKENS);
    red[t] = (float)NUM_EXP * f * P;
    __syncthreads();
#pragma unroll
    for (int s = NUM_EXP / 2; s > 0; s >>= 1) {
        if (t < s) red[t] += red[t + s];
        __syncthreads();
    }
    if (t == 0) out[OUT_AUX_OFF] = red[0];
}

extern "C" void kernel_launch(void* const* d_in, const int* in_sizes, int n_in,
                              void* d_out, int out_size) {
    const float* H = (const float*)d_in[0];  // [16384, 4096] fp32
    const float* W = (const float*)d_in[1];  // [64, 4096]    fp32
    float* out = (float*)d_out;
    (void)in_sizes; (void)n_in; (void)out_size;

    static bool attr_set = false;
    if (!attr_set) {
        cudaFuncSetAttribute(router_mma_kernel,
                             cudaFuncAttributeMaxDynamicSharedMemorySize, SMEM_DYN);
        attr_set = true;
    }

    wsplit_kernel<<<256, 256>>>(W);
    router_mma_kernel<<<NBLK, THREADS, SMEM_DYN>>>(H, out);
    router_aux_kernel<<<1, NUM_EXP>>>(out);
}

// round 6
// speedup vs baseline: 1.5248x; 1.0947x over previous
#include <cuda_runtime.h>
#include <math.h>
#include <cstdint>

// ---------------- problem constants ----------------
#define NUM_TOKENS 16384
#define EMBED_DIM  4096
#define NUM_EXP    64
#define TOPK       2

// ---------------- tiling ----------------
#define TPB     128                    // tokens per CTA (M)
#define KC      32                     // K elems per chunk
#define NCHUNK  (EMBED_DIM / KC)       // 128
#define THREADS 256                    // 8 warps
#define NBLK    (NUM_TOKENS / TPB)     // 128 CTAs

// smem (words): per stage A0[128][36], A1, B0[64][36], B1
#define PITCH   36
#define A0_W    0
#define A1_W    (128 * PITCH)          // 4608
#define B0_W    (2 * 128 * PITCH)      // 9216
#define B1_W    (B0_W + 64 * PITCH)    // 11520
#define STAGE_W (B1_W + 64 * PITCH)    // 13824 words = 55296 B
#define SMEM_DYN (2 * STAGE_W * 4)     // 110592 B

// output layout: [weights 2T][indices-as-float 2T][aux 1]
#define OUT_IDX_OFF (NUM_TOKENS * TOPK)
#define OUT_AUX_OFF (2 * NUM_TOKENS * TOPK)

__device__ float g_cnt[NUM_EXP];
__device__ float g_psum[NUM_EXP];
__device__ float g_W0[NUM_EXP * EMBED_DIM];
__device__ float g_W1[NUM_EXP * EMBED_DIM];

// tf32 convert with round-to-nearest (the numerically proven path)
__device__ __forceinline__ uint32_t to_tf32(float x) {
    uint32_t r;
    asm("cvt.rna.tf32.f32 %0, %1;" : "=r"(r) : "f"(x));
    return r;
}

__device__ __forceinline__ void mma_tf32(float* d, const uint32_t* a, const uint32_t* b) {
    asm volatile(
        "mma.sync.aligned.m16n8k8.row.col.f32.tf32.tf32.f32 "
        "{%0,%1,%2,%3}, {%4,%5,%6,%7}, {%8,%9}, {%0,%1,%2,%3};"
        : "+f"(d[0]), "+f"(d[1]), "+f"(d[2]), "+f"(d[3])
        : "r"(a[0]), "r"(a[1]), "r"(a[2]), "r"(a[3]), "r"(b[0]), "r"(b[1]));
}

// ---------------- prologue: zero accumulators + split W into tf32 limbs ----------------
__global__ void wsplit_kernel(const float* __restrict__ W) {
    if (blockIdx.x == 0 && threadIdx.x < NUM_EXP) {
        g_cnt[threadIdx.x] = 0.0f;
        g_psum[threadIdx.x] = 0.0f;
    }
    for (int i = blockIdx.x * blockDim.x + threadIdx.x; i < NUM_EXP * EMBED_DIM;
         i += gridDim.x * blockDim.x) {
        float x = W[i];
        float t0f = __uint_as_float(to_tf32(x));
        g_W0[i] = t0f;
        g_W1[i] = __uint_as_float(to_tf32(x - t0f));
    }
}

// ---------------- main kernel ----------------
__global__ __launch_bounds__(THREADS, 1)
void router_mma_kernel(const float* __restrict__ H, float* __restrict__ out) {
    extern __shared__ float dsm[];

    const int tid  = threadIdx.x;
    const int wid  = tid >> 5;
    const int lane = tid & 31;
    const int mg   = wid & 3;          // m-group: tokens mg*32..mg*32+31
    const int ng   = wid >> 2;         // n-group: experts ng*32..ng*32+31
    const int tb   = blockIdx.x * TPB;

    const float* __restrict__ Hbase = H + (size_t)tb * EMBED_DIM;

    float acc[2][4][4];
#pragma unroll
    for (int mt = 0; mt < 2; ++mt)
#pragma unroll
        for (int nt = 0; nt < 4; ++nt)
#pragma unroll
            for (int r = 0; r < 4; ++r) acc[mt][nt][r] = 0.0f;

    // prefetch registers for one chunk
    float4 hreg[4];    // H raw:   128x32 / 256thr = 4 float4
    float4 wreg[4];    // W limbs: 2x64x32 / 256thr = 4 float4

#define LOAD_CHUNK(c)                                                           \
    do {                                                                        \
        const int k0 = (c) * KC;                                                \
        _Pragma("unroll")                                                       \
        for (int i = 0; i < 4; ++i) {                                           \
            int idx = tid + (i << 8);        /* 0..1023 */                      \
            int r = idx >> 3, q = idx & 7;                                      \
            hreg[i] = *reinterpret_cast<const float4*>(                         \
                Hbase + (size_t)r * EMBED_DIM + k0 + (q << 2));                 \
        }                                                                       \
        _Pragma("unroll")                                                       \
        for (int i = 0; i < 4; ++i) {                                           \
            int idx = tid + (i << 8);                                           \
            int limb = idx >> 9, idx2 = idx & 511;                              \
            int r = idx2 >> 3, q = idx2 & 7;                                    \
            const float* Wp = limb ? g_W1 : g_W0;                               \
            wreg[i] = *reinterpret_cast<const float4*>(                         \
                Wp + (size_t)r * EMBED_DIM + k0 + (q << 2));                    \
        }                                                                       \
    } while (0)

// store chunk from regs into stage: split A into limbs here (cvt.rna for limb0,
// exact fp32 residual for limb1 — HW tf32 truncation of the residual is <=2^-21)
#define STORE_CHUNK(stage)                                                      \
    do {                                                                        \
        float* sb = dsm + (stage) * STAGE_W;                                    \
        _Pragma("unroll")                                                       \
        for (int i = 0; i < 4; ++i) {                                           \
            int idx = tid + (i << 8);                                           \
            int r = idx >> 3, q = idx & 7;                                      \
            int off = r * PITCH + (q << 2);                                     \
            float4 x = hreg[i];                                                 \
            float a0 = __uint_as_float(to_tf32(x.x));                           \
            float a1 = __uint_as_float(to_tf32(x.y));                           \
            float a2 = __uint_as_float(to_tf32(x.z));                           \
            float a3 = __uint_as_float(to_tf32(x.w));                           \
            *reinterpret_cast<float4*>(sb + A0_W + off) =                       \
                make_float4(a0, a1, a2, a3);                                    \
            *reinterpret_cast<float4*>(sb + A1_W + off) =                       \
                make_float4(x.x - a0, x.y - a1, x.z - a2, x.w - a3);            \
        }                                                                       \
        _Pragma("unroll")                                                       \
        for (int i = 0; i < 4; ++i) {                                           \
            int idx = tid + (i << 8);                                           \
            int limb = idx >> 9, idx2 = idx & 511;                              \
            int r = idx2 >> 3, q = idx2 & 7;                                    \
            int off = (limb ? B1_W : B0_W) + r * PITCH + (q << 2);              \
            *reinterpret_cast<float4*>(sb + off) = wreg[i];                     \
        }                                                                       \
    } while (0)

    // per-thread fragment offsets
    const int arow = (lane >> 2);      // 0..7
    const int acol = (lane & 3);       // 0..3

    // prologue: fill stage 0, prefetch chunk 1
    LOAD_CHUNK(0);
    STORE_CHUNK(0);
    LOAD_CHUNK(1);

    for (int c = 0; c < NCHUNK; ++c) {
        __syncthreads();   // stage (c&1) ready; stage ((c+1)&1) free (reused from c-1)

        if (c + 1 < NCHUNK) {
            STORE_CHUNK((c + 1) & 1);
            if (c + 2 < NCHUNK) LOAD_CHUNK(c + 2);
        }

        // ---- MMA over chunk c from stage c&1 ----
        const uint32_t* sbu = reinterpret_cast<const uint32_t*>(dsm + (c & 1) * STAGE_W);
#pragma unroll
        for (int ks = 0; ks < 4; ++ks) {
            const int k0 = ks << 3;
            uint32_t af[2][2][4];   // [mt][limb][reg]
            uint32_t bf[4][2][2];   // [nt][limb][reg]
#pragma unroll
            for (int mt = 0; mt < 2; ++mt) {
                int rb = (mg << 5) + (mt << 4) + arow;
#pragma unroll
                for (int l = 0; l < 2; ++l) {
                    int base = (l ? A1_W : A0_W) + rb * PITCH + k0 + acol;
                    af[mt][l][0] = sbu[base];
                    af[mt][l][1] = sbu[base + 8 * PITCH];
                    af[mt][l][2] = sbu[base + 4];
                    af[mt][l][3] = sbu[base + 8 * PITCH + 4];
                }
            }
#pragma unroll
            for (int nt = 0; nt < 4; ++nt) {
                int nb = (ng << 5) + (nt << 3) + arow;
#pragma unroll
                for (int l = 0; l < 2; ++l) {
                    int base = (l ? B1_W : B0_W) + nb * PITCH + k0 + acol;
                    bf[nt][l][0] = sbu[base];
                    bf[nt][l][1] = sbu[base + 4];
                }
            }
#pragma unroll
            for (int mt = 0; mt < 2; ++mt)
#pragma unroll
                for (int nt = 0; nt < 4; ++nt) {
                    mma_tf32(acc[mt][nt], af[mt][0], bf[nt][0]);  // a0*b0
                    mma_tf32(acc[mt][nt], af[mt][0], bf[nt][1]);  // a0*b1
                    mma_tf32(acc[mt][nt], af[mt][1], bf[nt][0]);  // a1*b0
                }
        }
    }
    __syncthreads();   // all MMAs done before overwriting smem with logits

    // ---- write logits to smem: lg[128][65] ----
    float* lg = dsm;
#pragma unroll
    for (int mt = 0; mt < 2; ++mt) {
        int row0 = (mg << 5) + (mt << 4) + arow;
#pragma unroll
        for (int nt = 0; nt < 4; ++nt) {
            int col0 = (ng << 5) + (nt << 3) + (acol << 1);
            lg[row0 * 65 + col0]           = acc[mt][nt][0];
            lg[row0 * 65 + col0 + 1]       = acc[mt][nt][1];
            lg[(row0 + 8) * 65 + col0]     = acc[mt][nt][2];
            lg[(row0 + 8) * 65 + col0 + 1] = acc[mt][nt][3];
        }
    }
    __syncthreads();

    // ---- per-token epilogue (threads 0..127) ----
    if (tid < TPB) {
        const float* row = lg + tid * 65;
        float v[NUM_EXP];
#pragma unroll
        for (int e = 0; e < NUM_EXP; ++e) v[e] = row[e];

        float m1 = -INFINITY; int i1 = 0;
#pragma unroll
        for (int e = 0; e < NUM_EXP; ++e)
            if (v[e] > m1) { m1 = v[e]; i1 = e; }
        float m2 = -INFINITY; int i2 = 0;
#pragma unroll
        for (int e = 0; e < NUM_EXP; ++e) {
            if (e == i1) continue;
            if (v[e] > m2) { m2 = v[e]; i2 = e; }
        }
        float dlt = expf(m2 - m1);
        float inv = 1.0f / (1.0f + dlt);
        int g = tb + tid;
        out[2 * g]     = inv;
        out[2 * g + 1] = dlt * inv;
        out[OUT_IDX_OFF + 2 * g]     = (float)i1;
        out[OUT_IDX_OFF + 2 * g + 1] = (float)i2;
        atomicAdd(&g_cnt[i1], 1.0f);
        atomicAdd(&g_cnt[i2], 1.0f);

        float ssum = 0.0f;
#pragma unroll
        for (int e = 0; e < NUM_EXP; ++e) {
            float p = expf(v[e] - m1);
            v[e] = p;
            ssum += p;
        }
        float is = 1.0f / ssum;
        float* wrow = lg + tid * 65;   // overwrite with probs
#pragma unroll
        for (int e = 0; e < NUM_EXP; ++e) wrow[e] = v[e] * is;
    }
    __syncthreads();

    if (tid < NUM_EXP) {
        float s = 0.0f;
#pragma unroll
        for (int t = 0; t < TPB; ++t) s += lg[t * 65 + tid];
        atomicAdd(&g_psum[tid], s);
    }
}

// ---------------- aux loss finalize ----------------
__global__ void router_aux_kernel(float* __restrict__ out) {
    __shared__ float red[NUM_EXP];
    int t = threadIdx.x;
    float f = g_cnt[t]  * (1.0f / (float)(NUM_TOKENS * TOPK));
    float P = g_psum[t] * (1.0f / (float)NUM_TOKENS);
    red[t] = (float)NUM_EXP * f * P;
    __syncthreads();
#pragma unroll
    for (int s = NUM_EXP / 2; s > 0; s >>= 1) {
        if (t < s) red[t] += red[t + s];
        __syncthreads();
    }
    if (t == 0) out[OUT_AUX_OFF] = red[0];
}

extern "C" void kernel_launch(void* const* d_in, const int* in_sizes, int n_in,
                              void* d_out, int out_size) {
    const float* H = (const float*)d_in[0];  // [16384, 4096] fp32
    const float* W = (const float*)d_in[1];  // [64, 4096]    fp32
    float* out = (float*)d_out;
    (void)in_sizes; (void)n_in; (void)out_size;

    static bool attr_set = false;
    if (!attr_set) {
        cudaFuncSetAttribute(router_mma_kernel,
                             cudaFuncAttributeMaxDynamicSharedMemorySize, SMEM_DYN);
        attr_set = true;
    }

    wsplit_kernel<<<256, 256>>>(W);
    router_mma_kernel<<<NBLK, THREADS, SMEM_DYN>>>(H, out);
    router_aux_kernel<<<1, NUM_EXP>>>(out);
}